// round 11
// baseline (speedup 1.0000x reference)
#include <cuda_runtime.h>
#include <cuda_bf16.h>

// GroupEmbedding: out[b,g,d] = sum_f x[b, group_idx[g,f]] * W[g,f,d] + bias[g,d]
// zeroed where masked_group_idx[b] == g.
// B=8192, NF=128, G=16, F=8, D=512. HBM-write-bound (256 MB out).
//
// R6: single-wave grid (1024 blocks @ 8/SM = 1184 slots), streaming stores,
//     2-row inner loop on transposed xs[f][r] (LDS.64 broadcast, 2 STG.128/iter).

#define B_TOTAL  8192
#define NF_      128
#define G_       16
#define F_       8
#define D_       512
#define D4_      (D_ / 4)       // 128 float4 per (b,g)
#define BROWS    128            // rows per block  -> grid = 16 x 64 = 1024 blocks
#define NTHREADS 128            // one thread per d4 column
#define XS_PAD   4              // stride 132: (132 mod 32)=4 -> conflict-free transpose store

__global__ __launch_bounds__(NTHREADS, 8)
void group_embedding_kernel(const float* __restrict__ x,
                            const float* __restrict__ W,
                            const float* __restrict__ bias,
                            const int*   __restrict__ gidx_raw,   // int32 view; may be int64
                            const int*   __restrict__ mgi_raw,    // int32 view; may be int64
                            float*       __restrict__ out)
{
    const int g  = blockIdx.x;          // 0..15
    const int b0 = blockIdx.y * BROWS;  // row tile base
    const int t  = threadIdx.x;         // 0..127 -> d4 column

    __shared__ float xs[F_][BROWS + XS_PAD];  // transposed: consecutive rows contiguous
    __shared__ int   msk[BROWS];
    __shared__ int   cols[F_];
    __shared__ int   flags;             // bit0: gidx is int32; bit1: mgi is int32

    // --- dtype detection: int64 LE values (<128) have all-zero odd 32-bit words ---
    if (t < 32) {
        int pg = gidx_raw[2 * t + 1];
        int pm = mgi_raw[2 * t + 1];
        int gi32 = __any_sync(0xffffffffu, pg != 0);
        int mi32 = __any_sync(0xffffffffu, pm != 0);
        if (t == 0) flags = (gi32 ? 1 : 0) | (mi32 ? 2 : 0);
    }
    __syncthreads();
    const bool gidx_i32 = (flags & 1) != 0;
    const bool mgi_i32  = (flags & 2) != 0;

    if (t < F_) {
        int idx = g * F_ + t;
        cols[t] = gidx_i32 ? gidx_raw[idx] : gidx_raw[2 * idx];
    }
    __syncthreads();

    // --- W column (8 float4) and bias into registers; reused for 128 rows ---
    const float4* __restrict__ W4 = (const float4*)W;
    float4 w[F_];
#pragma unroll
    for (int f = 0; f < F_; f++)
        w[f] = W4[(g * F_ + f) * D4_ + t];
    const float4 bb = ((const float4*)bias)[g * D4_ + t];

    // --- gather x tile (row-major reads, transposed shared stores) + masks ---
#pragma unroll
    for (int i = t; i < BROWS * F_; i += NTHREADS) {
        int r = i >> 3, f = i & 7;
        xs[f][r] = x[(b0 + r) * NF_ + cols[f]];
    }
    {
        int b = b0 + t;
        msk[t] = mgi_i32 ? mgi_raw[b] : mgi_raw[2 * b];
    }
    __syncthreads();

    // --- mainloop: 2 rows/iter, 8 LDS.64 broadcast + 64 FFMA + 2 streaming STG.128 ---
    const int ROWSTRIDE = G_ * D4_;   // float4 units between consecutive b rows
    float4* __restrict__ p =
        (float4*)out + ((size_t)b0 * G_ + (size_t)g) * D4_ + t;

#pragma unroll 4
    for (int r = 0; r < BROWS; r += 2) {
        float4 a0 = bb, a1 = bb;
#pragma unroll
        for (int f = 0; f < F_; f++) {
            const float2 xv = *(const float2*)&xs[f][r];   // rows r, r+1 (broadcast)
            a0.x = fmaf(xv.x, w[f].x, a0.x);
            a0.y = fmaf(xv.x, w[f].y, a0.y);
            a0.z = fmaf(xv.x, w[f].z, a0.z);
            a0.w = fmaf(xv.x, w[f].w, a0.w);
            a1.x = fmaf(xv.y, w[f].x, a1.x);
            a1.y = fmaf(xv.y, w[f].y, a1.y);
            a1.z = fmaf(xv.y, w[f].z, a1.z);
            a1.w = fmaf(xv.y, w[f].w, a1.w);
        }
        if (msk[r]     == g) a0 = make_float4(0.f, 0.f, 0.f, 0.f);
        if (msk[r + 1] == g) a1 = make_float4(0.f, 0.f, 0.f, 0.f);
        __stcs(p,             a0);     // streaming: output is write-only, bypass L2 retention
        __stcs(p + ROWSTRIDE, a1);
        p += 2 * ROWSTRIDE;
    }
}

extern "C" void kernel_launch(void* const* d_in, const int* in_sizes, int n_in,
                              void* d_out, int out_size)
{
    const float* x    = (const float*)d_in[0];
    const float* W    = (const float*)d_in[1];
    const float* bias = (const float*)d_in[2];
    const int*   gidx = (const int*)d_in[3];
    const int*   mgi  = (const int*)d_in[4];
    float*       out  = (float*)d_out;

    dim3 grid(G_, B_TOTAL / BROWS);   // 16 x 64 = 1024 blocks -> one resident wave
    group_embedding_kernel<<<grid, NTHREADS>>>(x, W, bias, gidx, mgi, out);
}

// round 12
// speedup vs baseline: 1.6353x; 1.6353x over previous
#include <cuda_runtime.h>
#include <cuda_bf16.h>

// GroupEmbedding: out[b,g,d] = sum_f x[b, group_idx[g,f]] * W[g,f,d] + bias[g,d]
// zeroed where masked_group_idx[b] == g.
// B=8192, NF=128, G=16, F=8, D=512. HBM-write-bound (256 MB out).
//
// R11: revert R6's __stcs + layout changes (regression: L1tex-saturated store path).
//      Keep R3's mainloop; fix wave quantization with a persistent 1184-block grid
//      (exactly one resident wave at 8 blocks/SM), each block looping over 16-row
//      chunks of its group with stride 74 (~1% load imbalance).

#define B_TOTAL  8192
#define NF_      128
#define G_       16
#define F_       8
#define D_       512
#define D4_      (D_ / 4)       // 128 float4 per (b,g)
#define CHUNK    16             // rows per chunk
#define NCHUNKS  (B_TOTAL / CHUNK)   // 512 chunks per group
#define JSTRIDE  74             // blocks per group: 16*74 = 1184 = one wave
#define NTHREADS 128            // one thread per d4 column

__global__ __launch_bounds__(NTHREADS)
void group_embedding_kernel(const float* __restrict__ x,
                            const float* __restrict__ W,
                            const float* __restrict__ bias,
                            const int*   __restrict__ gidx_raw,   // int32 view; may be int64
                            const int*   __restrict__ mgi_raw,    // int32 view; may be int64
                            float*       __restrict__ out)
{
    const int bx = blockIdx.x;
    const int g  = bx & 15;             // group: constant for this block
    const int j  = bx >> 4;             // 0..73, chunk stripe
    const int t  = threadIdx.x;         // 0..127 -> d4 column

    __shared__ float xs[CHUNK][F_];     // broadcast-read in compute: conflict-free
    __shared__ int   msk[CHUNK];
    __shared__ int   cols[F_];
    __shared__ int   flags;             // bit0: gidx is int32; bit1: mgi is int32

    // --- dtype detection: int64 LE values (<128) have all-zero odd 32-bit words ---
    if (t < 32) {
        int pg = gidx_raw[2 * t + 1];
        int pm = mgi_raw[2 * t + 1];
        int gi32 = __any_sync(0xffffffffu, pg != 0);
        int mi32 = __any_sync(0xffffffffu, pm != 0);
        if (t == 0) flags = (gi32 ? 1 : 0) | (mi32 ? 2 : 0);
    }
    __syncthreads();
    const bool gidx_i32 = (flags & 1) != 0;
    const bool mgi_i32  = (flags & 2) != 0;

    if (t < F_) {
        int idx = g * F_ + t;
        cols[t] = gidx_i32 ? gidx_raw[idx] : gidx_raw[2 * idx];
    }
    __syncthreads();

    // --- W column (8 float4) + bias into registers; reused for ALL chunks ---
    const float4* __restrict__ W4 = (const float4*)W;
    float4 w[F_];
#pragma unroll
    for (int f = 0; f < F_; f++)
        w[f] = W4[(g * F_ + f) * D4_ + t];
    const float4 bb = ((const float4*)bias)[g * D4_ + t];

    const int ROWSTRIDE = G_ * D4_;     // float4 units between consecutive b rows
    float4* __restrict__ out4 = (float4*)out;

    // --- persistent loop over this block's chunks (6-7 per block) ---
    for (int cb = j; cb < NCHUNKS; cb += JSTRIDE) {
        const int b0 = cb * CHUNK;

        // gather x tile: one load per thread (t>>3 = row, t&7 = feature)
        {
            int r = t >> 3, f = t & 7;
            xs[r][f] = x[(b0 + r) * NF_ + cols[f]];
            if (t < CHUNK)
                msk[t] = mgi_i32 ? mgi_raw[b0 + t] : mgi_raw[2 * (b0 + t)];
        }
        __syncthreads();

        float4* __restrict__ p = out4 + ((size_t)b0 * G_ + (size_t)g) * D4_ + t;
#pragma unroll
        for (int r = 0; r < CHUNK; r++) {
            float4 acc = bb;
#pragma unroll
            for (int f = 0; f < F_; f++) {
                const float xv = xs[r][f];
                acc.x = fmaf(xv, w[f].x, acc.x);
                acc.y = fmaf(xv, w[f].y, acc.y);
                acc.z = fmaf(xv, w[f].z, acc.z);
                acc.w = fmaf(xv, w[f].w, acc.w);
            }
            if (msk[r] == g) acc = make_float4(0.f, 0.f, 0.f, 0.f);
            p[0] = acc;                 // plain coalesced STG.128
            p += ROWSTRIDE;
        }
        __syncthreads();                // protect xs/msk before next gather
    }
}

extern "C" void kernel_launch(void* const* d_in, const int* in_sizes, int n_in,
                              void* d_out, int out_size)
{
    const float* x    = (const float*)d_in[0];
    const float* W    = (const float*)d_in[1];
    const float* bias = (const float*)d_in[2];
    const int*   gidx = (const int*)d_in[3];
    const int*   mgi  = (const int*)d_in[4];
    float*       out  = (float*)d_out;

    group_embedding_kernel<<<G_ * JSTRIDE, NTHREADS>>>(x, W, bias, gidx, mgi, out);
}